// round 10
// baseline (speedup 1.0000x reference)
#include <cuda_runtime.h>
#include <math_constants.h>
#include <cstdint>

#define C2LOG2E 2.8853900817779268f    // 2*log2(e)
#define LOG2E   1.4426950408889634f

// Scratch (no allocations allowed): per-(b,chunk) partial L and ctx[32].
__device__ float g_pl[8192];
__device__ float g_pctx[8192 * 32];
__device__ float g_invL[2048];

// NOTE: non-volatile on purpose — pure register computation; lets ptxas
// schedule around the ~25-cycle tensor-op latency.
__device__ __forceinline__ void mma_tf32(
    float& d0, float& d1, float& d2, float& d3,
    uint32_t a0, uint32_t a1, uint32_t a2, uint32_t a3,
    uint32_t b0, uint32_t b1)
{
    asm("mma.sync.aligned.m16n8k8.row.col.f32.tf32.tf32.f32 "
        "{%0,%1,%2,%3}, {%4,%5,%6,%7}, {%8,%9}, {%0,%1,%2,%3};"
        : "+f"(d0), "+f"(d1), "+f"(d2), "+f"(d3)
        : "r"(a0), "r"(a1), "r"(a2), "r"(a3), "r"(b0), "r"(b1));
}

__device__ __forceinline__ void tf32_split(float x, uint32_t& hi, uint32_t& lo)
{
    hi = __float_as_uint(x) & 0xFFFFE000u;
    lo = __float_as_uint(x - __uint_as_float(hi));
}

// Stage one 64-row group (32 floats/row) into smem at row stride 36 floats.
__device__ __forceinline__
void stage_group(const float* __restrict__ gRowBase, int rowsLeft,
                 float* __restrict__ xb, int lane)
{
    const char* gsrc = (const char*)gRowBase;
    const int maxIdx = rowsLeft * 8 - 1;
    #pragma unroll
    for (int k = 0; k < 16; ++k) {
        const int idx = k * 32 + lane;               // 0..511
        const int row = idx >> 3, c = idx & 7;
        unsigned long long saddr =
            __cvta_generic_to_shared(xb + row * 36 + c * 4);
        const char* src = gsrc + (size_t)min(idx, maxIdx) * 16;
        asm volatile("cp.async.cg.shared.global [%0], [%1], 16;"
                     :: "l"(saddr), "l"(src));
    }
}

// ---------------------------------------------------------------------------
// Kernel 1: grid (nChunk, B), 128 threads, 3 CTAs/SM. Each CTA covers 1024
// rows of one batch; warp sweeps 4 x 64-row groups, double-buffered cp.async.
// Keys GEMM on tensor cores (m16n8k8 tf32, 3xTF32, pass-major issue order).
// No-max softmax: unnormalized p straight to out_w; (L, ctx[32]) to scratch.
// ---------------------------------------------------------------------------
__global__ __launch_bounds__(128, 3)
void attn_main(const float* __restrict__ lstm, const float* __restrict__ fh,
               const float* __restrict__ Wq, const float* __restrict__ bq,
               const float* __restrict__ Wk, const float* __restrict__ bk,
               const float* __restrict__ Wv, const float* __restrict__ bv,
               float* __restrict__ out_w, int S)
{
    const int chunk = blockIdx.x;
    const int b     = blockIdx.y;
    const int tid   = threadIdx.x;
    const int w     = tid >> 5;
    const int lane  = tid & 31;
    const int g8    = lane >> 2;
    const int t4    = lane & 3;

    extern __shared__ __align__(16) float sX[];      // 4 warps * 2 * 2304

    __shared__ __align__(16) float sQC[32];
    __shared__ float sCtxW[128], sLw[4], sW1;

    float* xb0 = sX + w * 4608;
    const size_t rowB = (size_t)b * S;
    const int cbase = chunk * 1024;

    // ---- prefetch group 0 ----
    {
        const int base = cbase + w * 64;
        if (base < S)
            stage_group(lstm + (rowB + base) * 32, S - base, xb0, lane);
        asm volatile("cp.async.commit_group;");
    }

    // ---- prologue: query GEMV (overlaps group-0 DRAM latency) ----
    if (tid < 32) {
        float acc = bq[tid];
        #pragma unroll
        for (int h = 0; h < 32; ++h)
            acc = fmaf(fh[b * 32 + h], Wq[h * 32 + tid], acc);
        sQC[tid] = acc;
        float t = Wv[tid];
        #pragma unroll
        for (int off = 16; off; off >>= 1)
            t += __shfl_xor_sync(0xffffffffu, t, off);
        if (tid == 0) sW1 = bv[0] + t;
    }

    // ---- Wk fragments (hi/lo) in registers: B[k][n] = Wk[k*32+n] ----
    uint32_t Bhi[4][4][2], Blo[4][4][2];
    #pragma unroll
    for (int kt = 0; kt < 4; ++kt)
        #pragma unroll
        for (int nt = 0; nt < 4; ++nt) {
            const int n = nt * 8 + g8;
            const float f0 = Wk[(kt * 8 + t4) * 32 + n];
            const float f1 = Wk[(kt * 8 + t4 + 4) * 32 + n];
            tf32_split(f0, Bhi[kt][nt][0], Blo[kt][nt][0]);
            tf32_split(f1, Bhi[kt][nt][1], Blo[kt][nt][1]);
        }

    __syncthreads();

    // ---- per-lane column constants (slot s -> col = (s>>1)*8+2*t4+(s&1)) --
    float qck[8], nwv[8];
    #pragma unroll
    for (int s = 0; s < 8; ++s) {
        const int col = (s >> 1) * 8 + 2 * t4 + (s & 1);
        nwv[s] = -2.f * Wv[col];
        qck[s] = (sQC[col] + bk[col]) * C2LOG2E;
    }
    const float w1l = sW1 * LOG2E;

    float l = 0.f;
    float ctxD[8];
    #pragma unroll
    for (int s = 0; s < 8; ++s) ctxD[s] = 0.f;

    // ---- main sweep: 4 groups of 64 rows per warp ----
    #pragma unroll 1
    for (int gi = 0; gi < 4; ++gi) {
        if (gi + 1 < 4) {
            const int nb = cbase + (gi + 1) * 256 + w * 64;
            if (nb < S)
                stage_group(lstm + (rowB + nb) * 32, S - nb,
                            xb0 + ((gi + 1) & 1) * 2304, lane);
            asm volatile("cp.async.commit_group;");
            asm volatile("cp.async.wait_group 1;");
        } else {
            asm volatile("cp.async.wait_group 0;");
        }
        __syncwarp();

        const int gs = cbase + gi * 256 + w * 64;
        if (gs >= S) continue;
        const float* xg = xb0 + (gi & 1) * 2304;

        #pragma unroll 1
        for (int mt = 0; mt < 4; ++mt) {
            // ---- GEMM: D[16] = X[mt-tile] @ Wk (3xTF32, pass-major) ----
            float D[16];
            #pragma unroll
            for (int e = 0; e < 16; ++e) D[e] = 0.f;

            #pragma unroll
            for (int kt = 0; kt < 4; ++kt) {
                const int abase = (mt * 16 + g8) * 36 + kt * 8 + t4;
                uint32_t ah[4], al[4];
                tf32_split(xg[abase],       ah[0], al[0]);
                tf32_split(xg[abase + 288], ah[1], al[1]);   // +8 rows
                tf32_split(xg[abase + 4],   ah[2], al[2]);   // +4 k
                tf32_split(xg[abase + 292], ah[3], al[3]);

                // pass 0: Ahi x Bhi (same-acc issue distance = 4)
                #pragma unroll
                for (int nt = 0; nt < 4; ++nt)
                    mma_tf32(D[nt * 4], D[nt * 4 + 1], D[nt * 4 + 2],
                             D[nt * 4 + 3], ah[0], ah[1], ah[2], ah[3],
                             Bhi[kt][nt][0], Bhi[kt][nt][1]);
                // pass 1: Ahi x Blo
                #pragma unroll
                for (int nt = 0; nt < 4; ++nt)
                    mma_tf32(D[nt * 4], D[nt * 4 + 1], D[nt * 4 + 2],
                             D[nt * 4 + 3], ah[0], ah[1], ah[2], ah[3],
                             Blo[kt][nt][0], Blo[kt][nt][1]);
                // pass 2: Alo x Bhi
                #pragma unroll
                for (int nt = 0; nt < 4; ++nt)
                    mma_tf32(D[nt * 4], D[nt * 4 + 1], D[nt * 4 + 2],
                             D[nt * 4 + 3], al[0], al[1], al[2], al[3],
                             Bhi[kt][nt][0], Bhi[kt][nt][1]);
            }

            // ---- epilogue: rows r0 = gs+mt*16+g8, r1 = r0+8 ----
            const int r0 = gs + mt * 16 + g8;
            const int r1 = r0 + 8;
            const bool v0 = r0 < S, v1 = r1 < S;

            float s0 = 0.f, s1 = 0.f;
            #pragma unroll
            for (int nt = 0; nt < 4; ++nt)
                #pragma unroll
                for (int c = 0; c < 4; ++c) {
                    const int e = nt * 4 + c;
                    const int s = nt * 2 + (c & 1);
                    const float arg = fmaf(D[e], C2LOG2E, qck[s]);
                    float ex, rc;
                    asm("ex2.approx.f32 %0, %1;" : "=f"(ex) : "f"(arg));
                    asm("rcp.approx.f32 %0, %1;" : "=f"(rc) : "f"(ex + 1.f));
                    if (c < 2) s0 = fmaf(rc, nwv[s], s0);
                    else       s1 = fmaf(rc, nwv[s], s1);
                }

            s0 += __shfl_xor_sync(0xffffffffu, s0, 1);
            s0 += __shfl_xor_sync(0xffffffffu, s0, 2);
            s1 += __shfl_xor_sync(0xffffffffu, s1, 1);
            s1 += __shfl_xor_sync(0xffffffffu, s1, 2);

            float p0, p1;
            asm("ex2.approx.f32 %0, %1;" : "=f"(p0)
                : "f"(fmaf(s0, LOG2E, w1l)));
            asm("ex2.approx.f32 %0, %1;" : "=f"(p1)
                : "f"(fmaf(s1, LOG2E, w1l)));
            if (!v0) p0 = 0.f;
            if (!v1) p1 = 0.f;

            if (t4 == 0) {                          // unnormalized p -> gmem
                if (v0) out_w[rowB + r0] = p0;
                if (v1) out_w[rowB + r1] = p1;
            }

            l += p0 + p1;
            #pragma unroll
            for (int nt = 0; nt < 4; ++nt)
                #pragma unroll
                for (int bit = 0; bit < 2; ++bit) {
                    const int s = nt * 2 + bit;
                    ctxD[s] = fmaf(p0, D[nt * 4 + bit],
                              fmaf(p1, D[nt * 4 + 2 + bit], ctxD[s]));
                }
        }
    }

    // ---- warp reduce: l (/4 quad dup) and ctxD ----
    #pragma unroll
    for (int off = 16; off; off >>= 1)
        l += __shfl_xor_sync(0xffffffffu, l, off);
    l *= 0.25f;

    #pragma unroll
    for (int s = 0; s < 8; ++s) {
        ctxD[s] += __shfl_xor_sync(0xffffffffu, ctxD[s], 4);
        ctxD[s] += __shfl_xor_sync(0xffffffffu, ctxD[s], 8);
        ctxD[s] += __shfl_xor_sync(0xffffffffu, ctxD[s], 16);
    }
    if (g8 == 0) {
        #pragma unroll
        for (int s = 0; s < 8; ++s) {
            const int col = (s >> 1) * 8 + 2 * t4 + (s & 1);
            sCtxW[w * 32 + col] = ctxD[s];
        }
    }
    if (lane == 0) sLw[w] = l;
    __syncthreads();

    // ---- per-CTA partial out ----
    if (tid < 32) {
        float L = 0.f, ct = 0.f;
        #pragma unroll
        for (int ww = 0; ww < 4; ++ww) {
            L  += sLw[ww];
            ct += sCtxW[ww * 32 + tid];
        }
        const int pc = b * gridDim.x + chunk;
        g_pctx[pc * 32 + tid] = ct;
        if (tid == 0) g_pl[pc] = L;
    }
}

// ---------------------------------------------------------------------------
// Kernel 2: per-b merge of chunk partials -> context output + 1/L scratch.
// ---------------------------------------------------------------------------
__global__ __launch_bounds__(32)
void attn_merge(const float* __restrict__ bk, float* __restrict__ out_ctx,
                int nCh)
{
    const int b = blockIdx.x;
    const int d = threadIdx.x;

    float L = 0.f, ct = 0.f;
    for (int c = 0; c < nCh; ++c) {
        L  += g_pl[b * nCh + c];
        ct += g_pctx[(b * nCh + c) * 32 + d];
    }
    const float invL = 1.f / L;
    out_ctx[b * 32 + d] = fmaf(ct, invL, bk[d]);       // + bk fold
    if (d == 0) g_invL[b] = invL;
}

// ---------------------------------------------------------------------------
// Kernel 3: wide normalize — weights = p * (1/L), pure multiply, float4.
// Grid (S/1024, B), 256 threads, one float4 per thread.
// ---------------------------------------------------------------------------
__global__ __launch_bounds__(256)
void attn_norm(float* __restrict__ out_w, int S)
{
    const int b  = blockIdx.y;
    const float inv = g_invL[b];
    float* base = out_w + (size_t)b * S;
    const int i4 = blockIdx.x * 256 + threadIdx.x;
    if (i4 * 4 + 3 < S) {
        float4* p = (float4*)base + i4;
        float4 v = *p;
        v.x *= inv; v.y *= inv; v.z *= inv; v.w *= inv;
        *p = v;
    } else {
        for (int i = i4 * 4; i < S; ++i) base[i] *= inv;
    }
}

// ---------------------------------------------------------------------------
extern "C" void kernel_launch(void* const* d_in, const int* in_sizes, int n_in,
                              void* d_out, int out_size)
{
    const float* lstm = (const float*)d_in[0];
    const float* fh   = (const float*)d_in[1];
    const float* Wq   = (const float*)d_in[2];
    const float* bq   = (const float*)d_in[3];
    const float* Wk   = (const float*)d_in[4];
    const float* bk   = (const float*)d_in[5];
    const float* Wv   = (const float*)d_in[6];
    const float* bv   = (const float*)d_in[7];

    const int BH = in_sizes[1];            // B * H
    const int B  = BH / 32;
    const int S  = in_sizes[0] / BH;
    const int nCh = (S + 1023) / 1024;     // 1024 rows per CTA

    float* out_ctx = (float*)d_out;                 // [B, 32]
    float* out_w   = out_ctx + (size_t)B * 32;      // [B, S]

    const int smemBytes = 4 * 4608 * (int)sizeof(float);   // 72 KB
    static int attrSet = 0;
    if (!attrSet) {
        cudaFuncSetAttribute(attn_main,
                             cudaFuncAttributeMaxDynamicSharedMemorySize,
                             smemBytes);
        attrSet = 1;
    }

    dim3 grid(nCh, B);
    attn_main<<<grid, 128, smemBytes>>>(lstm, fh, Wq, bq, Wk, bk, Wv, bv,
                                        out_w, S);
    attn_merge<<<B, 32>>>(bk, out_ctx, nCh);

    dim3 ngrid((S / 4 + 255) / 256, B);
    attn_norm<<<ngrid, 256>>>(out_w, S);
}

// round 11
// speedup vs baseline: 1.2826x; 1.2826x over previous
#include <cuda_runtime.h>
#include <math_constants.h>
#include <cstdint>

#define LOG2E 1.4426950408889634f

// Scratch (no allocations allowed): per-(b,chunk) partial L and ctx[32].
__device__ float g_pl[8192];
__device__ float g_pctx[8192 * 32];
__device__ float g_invL[2048];

// Non-volatile on purpose — pure register computation; ptxas schedules
// around the tensor-op latency.
__device__ __forceinline__ void mma_tf32(
    float& d0, float& d1, float& d2, float& d3,
    uint32_t a0, uint32_t a1, uint32_t a2, uint32_t a3,
    uint32_t b0, uint32_t b1)
{
    asm("mma.sync.aligned.m16n8k8.row.col.f32.tf32.tf32.f32 "
        "{%0,%1,%2,%3}, {%4,%5,%6,%7}, {%8,%9}, {%0,%1,%2,%3};"
        : "+f"(d0), "+f"(d1), "+f"(d2), "+f"(d3)
        : "r"(a0), "r"(a1), "r"(a2), "r"(a3), "r"(b0), "r"(b1));
}

__device__ __forceinline__ void tf32_split(float x, uint32_t& hi, uint32_t& lo)
{
    hi = __float_as_uint(x) & 0xFFFFE000u;
    lo = __float_as_uint(x - __uint_as_float(hi));
}

// Stage one 64-row group (32 floats/row) into smem at row stride 36 floats.
__device__ __forceinline__
void stage_group(const float* __restrict__ gRowBase, int rowsLeft,
                 float* __restrict__ xb, int lane)
{
    const char* gsrc = (const char*)gRowBase;
    const int maxIdx = rowsLeft * 8 - 1;
    #pragma unroll
    for (int k = 0; k < 16; ++k) {
        const int idx = k * 32 + lane;               // 0..511
        const int row = idx >> 3, c = idx & 7;
        unsigned long long saddr =
            __cvta_generic_to_shared(xb + row * 36 + c * 4);
        const char* src = gsrc + (size_t)min(idx, maxIdx) * 16;
        asm volatile("cp.async.cg.shared.global [%0], [%1], 16;"
                     :: "l"(saddr), "l"(src));
    }
}

// ---------------------------------------------------------------------------
// Kernel 1: grid (nChunk, B), 128 threads, 3 CTAs/SM. Each CTA covers 1024
// rows of one batch; warp sweeps 4 x 64-row groups, double-buffered cp.async.
// Keys GEMM on tensor cores (m16n8k8 tf32, 3xTF32, pass-major). Score uses
// HW tanh.approx (1 MUFU/element). No-max softmax: unnormalized p -> out_w.
// ---------------------------------------------------------------------------
__global__ __launch_bounds__(128, 3)
void attn_main(const float* __restrict__ lstm, const float* __restrict__ fh,
               const float* __restrict__ Wq, const float* __restrict__ bq,
               const float* __restrict__ Wk, const float* __restrict__ bk,
               const float* __restrict__ Wv, const float* __restrict__ bv,
               float* __restrict__ out_w, int S)
{
    const int chunk = blockIdx.x;
    const int b     = blockIdx.y;
    const int tid   = threadIdx.x;
    const int w     = tid >> 5;
    const int lane  = tid & 31;
    const int g8    = lane >> 2;
    const int t4    = lane & 3;

    extern __shared__ __align__(16) float sX[];      // 4 warps * 2 * 2304

    __shared__ __align__(16) float sQC[32];
    __shared__ float sCtxW[128], sLw[4];

    float* xb0 = sX + w * 4608;
    const size_t rowB = (size_t)b * S;
    const int cbase = chunk * 1024;

    // ---- prefetch group 0 ----
    {
        const int base = cbase + w * 64;
        if (base < S)
            stage_group(lstm + (rowB + base) * 32, S - base, xb0, lane);
        asm volatile("cp.async.commit_group;");
    }

    // ---- prologue: query GEMV (overlaps group-0 DRAM latency) ----
    if (tid < 32) {
        float acc = bq[tid];
        #pragma unroll
        for (int h = 0; h < 32; ++h)
            acc = fmaf(fh[b * 32 + h], Wq[h * 32 + tid], acc);
        sQC[tid] = acc;
    }

    // ---- Wk fragments (hi/lo) in registers: B[k][n] = Wk[k*32+n] ----
    uint32_t Bhi[4][4][2], Blo[4][4][2];
    #pragma unroll
    for (int kt = 0; kt < 4; ++kt)
        #pragma unroll
        for (int nt = 0; nt < 4; ++nt) {
            const int n = nt * 8 + g8;
            const float f0 = Wk[(kt * 8 + t4) * 32 + n];
            const float f1 = Wk[(kt * 8 + t4 + 4) * 32 + n];
            tf32_split(f0, Bhi[kt][nt][0], Blo[kt][nt][0]);
            tf32_split(f1, Bhi[kt][nt][1], Blo[kt][nt][1]);
        }

    __syncthreads();

    // ---- per-lane column constants (slot s -> col = (s>>1)*8+2*t4+(s&1)) --
    float qbk[8], wvv[8];
    #pragma unroll
    for (int s = 0; s < 8; ++s) {
        const int col = (s >> 1) * 8 + 2 * t4 + (s & 1);
        wvv[s] = Wv[col];
        qbk[s] = sQC[col] + bk[col];
    }
    const float w1l = bv[0] * LOG2E;     // p = exp2(score*log2e + bv*log2e)

    float l = 0.f;
    float ctxD[8];
    #pragma unroll
    for (int s = 0; s < 8; ++s) ctxD[s] = 0.f;

    // ---- main sweep: 4 groups of 64 rows per warp ----
    #pragma unroll 1
    for (int gi = 0; gi < 4; ++gi) {
        if (gi + 1 < 4) {
            const int nb = cbase + (gi + 1) * 256 + w * 64;
            if (nb < S)
                stage_group(lstm + (rowB + nb) * 32, S - nb,
                            xb0 + ((gi + 1) & 1) * 2304, lane);
            asm volatile("cp.async.commit_group;");
            asm volatile("cp.async.wait_group 1;");
        } else {
            asm volatile("cp.async.wait_group 0;");
        }
        __syncwarp();

        const int gs = cbase + gi * 256 + w * 64;
        if (gs >= S) continue;
        const float* xg = xb0 + (gi & 1) * 2304;

        #pragma unroll 1
        for (int mt = 0; mt < 4; ++mt) {
            // ---- GEMM: D[16] = X[mt-tile] @ Wk (3xTF32, pass-major) ----
            float D[16];
            #pragma unroll
            for (int e = 0; e < 16; ++e) D[e] = 0.f;

            #pragma unroll
            for (int kt = 0; kt < 4; ++kt) {
                const int abase = (mt * 16 + g8) * 36 + kt * 8 + t4;
                uint32_t ah[4], al[4];
                tf32_split(xg[abase],       ah[0], al[0]);
                tf32_split(xg[abase + 288], ah[1], al[1]);   // +8 rows
                tf32_split(xg[abase + 4],   ah[2], al[2]);   // +4 k
                tf32_split(xg[abase + 292], ah[3], al[3]);

                #pragma unroll
                for (int nt = 0; nt < 4; ++nt)
                    mma_tf32(D[nt * 4], D[nt * 4 + 1], D[nt * 4 + 2],
                             D[nt * 4 + 3], ah[0], ah[1], ah[2], ah[3],
                             Bhi[kt][nt][0], Bhi[kt][nt][1]);
                #pragma unroll
                for (int nt = 0; nt < 4; ++nt)
                    mma_tf32(D[nt * 4], D[nt * 4 + 1], D[nt * 4 + 2],
                             D[nt * 4 + 3], ah[0], ah[1], ah[2], ah[3],
                             Blo[kt][nt][0], Blo[kt][nt][1]);
                #pragma unroll
                for (int nt = 0; nt < 4; ++nt)
                    mma_tf32(D[nt * 4], D[nt * 4 + 1], D[nt * 4 + 2],
                             D[nt * 4 + 3], al[0], al[1], al[2], al[3],
                             Bhi[kt][nt][0], Bhi[kt][nt][1]);
            }

            // ---- epilogue: rows r0 = gs+mt*16+g8, r1 = r0+8 ----
            const int r0 = gs + mt * 16 + g8;
            const int r1 = r0 + 8;
            const bool v0 = r0 < S, v1 = r1 < S;

            float s0 = 0.f, s1 = 0.f;
            #pragma unroll
            for (int nt = 0; nt < 4; ++nt)
                #pragma unroll
                for (int c = 0; c < 4; ++c) {
                    const int e = nt * 4 + c;
                    const int s = nt * 2 + (c & 1);
                    float t;                          // HW tanh: 1 MUFU op
                    asm("tanh.approx.f32 %0, %1;"
                        : "=f"(t) : "f"(D[e] + qbk[s]));
                    if (c < 2) s0 = fmaf(t, wvv[s], s0);
                    else       s1 = fmaf(t, wvv[s], s1);
                }

            s0 += __shfl_xor_sync(0xffffffffu, s0, 1);
            s0 += __shfl_xor_sync(0xffffffffu, s0, 2);
            s1 += __shfl_xor_sync(0xffffffffu, s1, 1);
            s1 += __shfl_xor_sync(0xffffffffu, s1, 2);

            float p0, p1;
            asm("ex2.approx.f32 %0, %1;" : "=f"(p0)
                : "f"(fmaf(s0, LOG2E, w1l)));
            asm("ex2.approx.f32 %0, %1;" : "=f"(p1)
                : "f"(fmaf(s1, LOG2E, w1l)));
            if (!v0) p0 = 0.f;
            if (!v1) p1 = 0.f;

            if (t4 == 0) {                           // unnormalized p -> gmem
                if (v0) out_w[rowB + r0] = p0;
                if (v1) out_w[rowB + r1] = p1;
            }

            l += p0 + p1;
            #pragma unroll
            for (int nt = 0; nt < 4; ++nt)
                #pragma unroll
                for (int bit = 0; bit < 2; ++bit) {
                    const int s = nt * 2 + bit;
                    ctxD[s] = fmaf(p0, D[nt * 4 + bit],
                              fmaf(p1, D[nt * 4 + 2 + bit], ctxD[s]));
                }
        }
    }

    // ---- warp reduce: l (/4 quad dup) and ctxD ----
    #pragma unroll
    for (int off = 16; off; off >>= 1)
        l += __shfl_xor_sync(0xffffffffu, l, off);
    l *= 0.25f;

    #pragma unroll
    for (int s = 0; s < 8; ++s) {
        ctxD[s] += __shfl_xor_sync(0xffffffffu, ctxD[s], 4);
        ctxD[s] += __shfl_xor_sync(0xffffffffu, ctxD[s], 8);
        ctxD[s] += __shfl_xor_sync(0xffffffffu, ctxD[s], 16);
    }
    if (g8 == 0) {
        #pragma unroll
        for (int s = 0; s < 8; ++s) {
            const int col = (s >> 1) * 8 + 2 * t4 + (s & 1);
            sCtxW[w * 32 + col] = ctxD[s];
        }
    }
    if (lane == 0) sLw[w] = l;
    __syncthreads();

    // ---- per-CTA partial out ----
    if (tid < 32) {
        float L = 0.f, ct = 0.f;
        #pragma unroll
        for (int ww = 0; ww < 4; ++ww) {
            L  += sLw[ww];
            ct += sCtxW[ww * 32 + tid];
        }
        const int pc = b * gridDim.x + chunk;
        g_pctx[pc * 32 + tid] = ct;
        if (tid == 0) g_pl[pc] = L;
    }
}

// ---------------------------------------------------------------------------
// Kernel 2: per-b merge of chunk partials -> context output + 1/L scratch.
// ---------------------------------------------------------------------------
__global__ __launch_bounds__(32)
void attn_merge(const float* __restrict__ bk, float* __restrict__ out_ctx,
                int nCh)
{
    const int b = blockIdx.x;
    const int d = threadIdx.x;

    float L = 0.f, ct = 0.f;
    for (int c = 0; c < nCh; ++c) {
        L  += g_pl[b * nCh + c];
        ct += g_pctx[(b * nCh + c) * 32 + d];
    }
    const float invL = 1.f / L;
    out_ctx[b * 32 + d] = fmaf(ct, invL, bk[d]);       // + bk fold
    if (d == 0) g_invL[b] = invL;
}

// ---------------------------------------------------------------------------
// Kernel 3: wide normalize — weights = p * (1/L), pure multiply, float4.
// ---------------------------------------------------------------------------
__global__ __launch_bounds__(256)
void attn_norm(float* __restrict__ out_w, int S)
{
    const int b  = blockIdx.y;
    const float inv = g_invL[b];
    float* base = out_w + (size_t)b * S;
    const int i4 = blockIdx.x * 256 + threadIdx.x;
    if (i4 * 4 + 3 < S) {
        float4* p = (float4*)base + i4;
        float4 v = *p;
        v.x *= inv; v.y *= inv; v.z *= inv; v.w *= inv;
        *p = v;
    } else {
        for (int i = i4 * 4; i < S; ++i) base[i] *= inv;
    }
}

// ---------------------------------------------------------------------------
extern "C" void kernel_launch(void* const* d_in, const int* in_sizes, int n_in,
                              void* d_out, int out_size)
{
    const float* lstm = (const float*)d_in[0];
    const float* fh   = (const float*)d_in[1];
    const float* Wq   = (const float*)d_in[2];
    const float* bq   = (const float*)d_in[3];
    const float* Wk   = (const float*)d_in[4];
    const float* bk   = (const float*)d_in[5];
    const float* Wv   = (const float*)d_in[6];
    const float* bv   = (const float*)d_in[7];

    const int BH = in_sizes[1];            // B * H
    const int B  = BH / 32;
    const int S  = in_sizes[0] / BH;
    const int nCh = (S + 1023) / 1024;     // 1024 rows per CTA

    float* out_ctx = (float*)d_out;                 // [B, 32]
    float* out_w   = out_ctx + (size_t)B * 32;      // [B, S]

    const int smemBytes = 4 * 4608 * (int)sizeof(float);   // 72 KB
    static int attrSet = 0;
    if (!attrSet) {
        cudaFuncSetAttribute(attn_main,
                             cudaFuncAttributeMaxDynamicSharedMemorySize,
                             smemBytes);
        attrSet = 1;
    }

    dim3 grid(nCh, B);
    attn_main<<<grid, 128, smemBytes>>>(lstm, fh, Wq, bq, Wk, bk, Wv, bv,
                                        out_w, S);
    attn_merge<<<B, 32>>>(bk, out_ctx, nCh);

    dim3 ngrid((S / 4 + 255) / 256, B);
    attn_norm<<<ngrid, 256>>>(out_w, S);
}

// round 12
// speedup vs baseline: 1.4763x; 1.1510x over previous
#include <cuda_runtime.h>
#include <math_constants.h>
#include <cstdint>

#define LOG2E 1.4426950408889634f

// Scratch (no allocations allowed): per-(b,chunk) partial L and ctx[32].
__device__ float g_pl[8192];
__device__ float g_pctx[8192 * 32];

// Non-volatile on purpose — pure register computation; ptxas schedules
// around the tensor-op latency.
__device__ __forceinline__ void mma_tf32(
    float& d0, float& d1, float& d2, float& d3,
    uint32_t a0, uint32_t a1, uint32_t a2, uint32_t a3,
    uint32_t b0, uint32_t b1)
{
    asm("mma.sync.aligned.m16n8k8.row.col.f32.tf32.tf32.f32 "
        "{%0,%1,%2,%3}, {%4,%5,%6,%7}, {%8,%9}, {%0,%1,%2,%3};"
        : "+f"(d0), "+f"(d1), "+f"(d2), "+f"(d3)
        : "r"(a0), "r"(a1), "r"(a2), "r"(a3), "r"(b0), "r"(b1));
}

// hi = truncation split (lo exact remainder): A = hi + lo with lo tiny.
__device__ __forceinline__ void tf32_split(float x, uint32_t& hi, uint32_t& lo)
{
    hi = __float_as_uint(x) & 0xFFFFE000u;
    lo = __float_as_uint(x - __uint_as_float(hi));
}

// round-to-nearest tf32 (for the single-pass B operand)
__device__ __forceinline__ uint32_t tf32_rna(float x)
{
    uint32_t r;
    asm("cvt.rna.tf32.f32 %0, %1;" : "=r"(r) : "f"(x));
    return r;
}

// Stage one 64-row group (32 floats/row) into smem at row stride 36 floats.
__device__ __forceinline__
void stage_group(const float* __restrict__ gRowBase, int rowsLeft,
                 float* __restrict__ xb, int lane)
{
    const char* gsrc = (const char*)gRowBase;
    const int maxIdx = rowsLeft * 8 - 1;
    #pragma unroll
    for (int k = 0; k < 16; ++k) {
        const int idx = k * 32 + lane;               // 0..511
        const int row = idx >> 3, c = idx & 7;
        unsigned long long saddr =
            __cvta_generic_to_shared(xb + row * 36 + c * 4);
        const char* src = gsrc + (size_t)min(idx, maxIdx) * 16;
        asm volatile("cp.async.cg.shared.global [%0], [%1], 16;"
                     :: "l"(saddr), "l"(src));
    }
}

// ---------------------------------------------------------------------------
// Kernel 1: grid (nChunk, B), 128 threads, 3 CTAs/SM. Each CTA covers 1024
// rows of one batch; warp sweeps 4 x 64-row groups, double-buffered cp.async.
// Keys GEMM: m16n8k8 tf32, 2-pass split-A (A exact, B rna-rounded tf32).
// Score uses HW tanh.approx. No-max softmax: unnormalized p -> out_w.
// ---------------------------------------------------------------------------
__global__ __launch_bounds__(128, 3)
void attn_main(const float* __restrict__ lstm, const float* __restrict__ fh,
               const float* __restrict__ Wq, const float* __restrict__ bq,
               const float* __restrict__ Wk, const float* __restrict__ bk,
               const float* __restrict__ Wv, const float* __restrict__ bv,
               float* __restrict__ out_w, int S)
{
    const int chunk = blockIdx.x;
    const int b     = blockIdx.y;
    const int tid   = threadIdx.x;
    const int w     = tid >> 5;
    const int lane  = tid & 31;
    const int g8    = lane >> 2;
    const int t4    = lane & 3;

    extern __shared__ __align__(16) float sX[];      // 4 warps * 2 * 2304

    __shared__ __align__(16) float sQC[32];
    __shared__ float sCtxW[128], sLw[4];

    float* xb0 = sX + w * 4608;
    const size_t rowB = (size_t)b * S;
    const int cbase = chunk * 1024;

    // ---- prefetch group 0 ----
    {
        const int base = cbase + w * 64;
        if (base < S)
            stage_group(lstm + (rowB + base) * 32, S - base, xb0, lane);
        asm volatile("cp.async.commit_group;");
    }

    // ---- prologue: query GEMV (overlaps group-0 DRAM latency) ----
    if (tid < 32) {
        float acc = bq[tid];
        #pragma unroll
        for (int h = 0; h < 32; ++h)
            acc = fmaf(fh[b * 32 + h], Wq[h * 32 + tid], acc);
        sQC[tid] = acc;
    }

    // ---- Wk fragments (single tf32, rna) : B[k][n] = Wk[k*32+n] ----
    uint32_t Bf[4][4][2];
    #pragma unroll
    for (int kt = 0; kt < 4; ++kt)
        #pragma unroll
        for (int nt = 0; nt < 4; ++nt) {
            const int n = nt * 8 + g8;
            Bf[kt][nt][0] = tf32_rna(Wk[(kt * 8 + t4) * 32 + n]);
            Bf[kt][nt][1] = tf32_rna(Wk[(kt * 8 + t4 + 4) * 32 + n]);
        }

    __syncthreads();

    // ---- per-lane column constants (slot s -> col = (s>>1)*8+2*t4+(s&1)) --
    float qbk[8], wvv[8];
    #pragma unroll
    for (int s = 0; s < 8; ++s) {
        const int col = (s >> 1) * 8 + 2 * t4 + (s & 1);
        wvv[s] = Wv[col];
        qbk[s] = sQC[col] + bk[col];
    }
    const float w1l = bv[0] * LOG2E;     // p = exp2(score*log2e + bv*log2e)

    float l = 0.f;
    float ctxD[8];
    #pragma unroll
    for (int s = 0; s < 8; ++s) ctxD[s] = 0.f;

    // ---- main sweep: 4 groups of 64 rows per warp ----
    #pragma unroll 1
    for (int gi = 0; gi < 4; ++gi) {
        if (gi + 1 < 4) {
            const int nb = cbase + (gi + 1) * 256 + w * 64;
            if (nb < S)
                stage_group(lstm + (rowB + nb) * 32, S - nb,
                            xb0 + ((gi + 1) & 1) * 2304, lane);
            asm volatile("cp.async.commit_group;");
            asm volatile("cp.async.wait_group 1;");
        } else {
            asm volatile("cp.async.wait_group 0;");
        }
        __syncwarp();

        const int gs = cbase + gi * 256 + w * 64;
        if (gs >= S) continue;
        const float* xg = xb0 + (gi & 1) * 2304;

        #pragma unroll 1
        for (int mt = 0; mt < 4; ++mt) {
            // ---- GEMM: D[16] = X[mt-tile] @ Wk (2-pass split-A) ----
            float D[16];
            #pragma unroll
            for (int e = 0; e < 16; ++e) D[e] = 0.f;

            #pragma unroll
            for (int kt = 0; kt < 4; ++kt) {
                const int abase = (mt * 16 + g8) * 36 + kt * 8 + t4;
                uint32_t ah[4], al[4];
                tf32_split(xg[abase],       ah[0], al[0]);
                tf32_split(xg[abase + 288], ah[1], al[1]);   // +8 rows
                tf32_split(xg[abase + 4],   ah[2], al[2]);   // +4 k
                tf32_split(xg[abase + 292], ah[3], al[3]);

                // pass 0: Ahi x B
                #pragma unroll
                for (int nt = 0; nt < 4; ++nt)
                    mma_tf32(D[nt * 4], D[nt * 4 + 1], D[nt * 4 + 2],
                             D[nt * 4 + 3], ah[0], ah[1], ah[2], ah[3],
                             Bf[kt][nt][0], Bf[kt][nt][1]);
                // pass 1: Alo x B  (A = Ahi + Alo exact)
                #pragma unroll
                for (int nt = 0; nt < 4; ++nt)
                    mma_tf32(D[nt * 4], D[nt * 4 + 1], D[nt * 4 + 2],
                             D[nt * 4 + 3], al[0], al[1], al[2], al[3],
                             Bf[kt][nt][0], Bf[kt][nt][1]);
            }

            // ---- epilogue: rows r0 = gs+mt*16+g8, r1 = r0+8 ----
            const int r0 = gs + mt * 16 + g8;
            const int r1 = r0 + 8;
            const bool v0 = r0 < S, v1 = r1 < S;

            float s0 = 0.f, s1 = 0.f;
            #pragma unroll
            for (int nt = 0; nt < 4; ++nt)
                #pragma unroll
                for (int c = 0; c < 4; ++c) {
                    const int e = nt * 4 + c;
                    const int s = nt * 2 + (c & 1);
                    float t;                          // HW tanh: 1 MUFU op
                    asm("tanh.approx.f32 %0, %1;"
                        : "=f"(t) : "f"(D[e] + qbk[s]));
                    if (c < 2) s0 = fmaf(t, wvv[s], s0);
                    else       s1 = fmaf(t, wvv[s], s1);
                }

            s0 += __shfl_xor_sync(0xffffffffu, s0, 1);
            s0 += __shfl_xor_sync(0xffffffffu, s0, 2);
            s1 += __shfl_xor_sync(0xffffffffu, s1, 1);
            s1 += __shfl_xor_sync(0xffffffffu, s1, 2);

            float p0, p1;
            asm("ex2.approx.f32 %0, %1;" : "=f"(p0)
                : "f"(fmaf(s0, LOG2E, w1l)));
            asm("ex2.approx.f32 %0, %1;" : "=f"(p1)
                : "f"(fmaf(s1, LOG2E, w1l)));
            if (!v0) p0 = 0.f;
            if (!v1) p1 = 0.f;

            if (t4 == 0) {                           // unnormalized p -> gmem
                if (v0) out_w[rowB + r0] = p0;
                if (v1) out_w[rowB + r1] = p1;
            }

            l += p0 + p1;
            #pragma unroll
            for (int nt = 0; nt < 4; ++nt)
                #pragma unroll
                for (int bit = 0; bit < 2; ++bit) {
                    const int s = nt * 2 + bit;
                    ctxD[s] = fmaf(p0, D[nt * 4 + bit],
                              fmaf(p1, D[nt * 4 + 2 + bit], ctxD[s]));
                }
        }
    }

    // ---- warp reduce: l (/4 quad dup) and ctxD ----
    #pragma unroll
    for (int off = 16; off; off >>= 1)
        l += __shfl_xor_sync(0xffffffffu, l, off);
    l *= 0.25f;

    #pragma unroll
    for (int s = 0; s < 8; ++s) {
        ctxD[s] += __shfl_xor_sync(0xffffffffu, ctxD[s], 4);
        ctxD[s] += __shfl_xor_sync(0xffffffffu, ctxD[s], 8);
        ctxD[s] += __shfl_xor_sync(0xffffffffu, ctxD[s], 16);
    }
    if (g8 == 0) {
        #pragma unroll
        for (int s = 0; s < 8; ++s) {
            const int col = (s >> 1) * 8 + 2 * t4 + (s & 1);
            sCtxW[w * 32 + col] = ctxD[s];
        }
    }
    if (lane == 0) sLw[w] = l;
    __syncthreads();

    // ---- per-CTA partial out ----
    if (tid < 32) {
        float L = 0.f, ct = 0.f;
        #pragma unroll
        for (int ww = 0; ww < 4; ++ww) {
            L  += sLw[ww];
            ct += sCtxW[ww * 32 + tid];
        }
        const int pc = b * gridDim.x + chunk;
        g_pctx[pc * 32 + tid] = ct;
        if (tid == 0) g_pl[pc] = L;
    }
}

// ---------------------------------------------------------------------------
// Kernel 2 (fused finish): every block recomputes L from the nCh partials
// (4 floats via L2 broadcast); block x==0 also merges ctx and writes it.
// Then normalize the unnormalized p row by 1/L (pure multiply, float4).
// ---------------------------------------------------------------------------
__global__ __launch_bounds__(256)
void attn_norm(const float* __restrict__ bk, float* __restrict__ out_ctx,
               float* __restrict__ out_w, int S, int nCh)
{
    const int b   = blockIdx.y;
    const int tid = threadIdx.x;

    float L = 0.f;
    for (int c = 0; c < nCh; ++c) L += g_pl[b * nCh + c];
    const float inv = 1.f / L;

    if (blockIdx.x == 0 && tid < 32) {
        float ct = 0.f;
        for (int c = 0; c < nCh; ++c)
            ct += g_pctx[(b * nCh + c) * 32 + tid];
        out_ctx[b * 32 + tid] = fmaf(ct, inv, bk[tid]);   // + bk fold
    }

    float* base = out_w + (size_t)b * S;
    const int i4 = blockIdx.x * 256 + tid;
    if (i4 * 4 + 3 < S) {
        float4* p = (float4*)base + i4;
        float4 v = *p;
        v.x *= inv; v.y *= inv; v.z *= inv; v.w *= inv;
        *p = v;
    } else {
        for (int i = i4 * 4; i < S; ++i) base[i] *= inv;
    }
}

// ---------------------------------------------------------------------------
extern "C" void kernel_launch(void* const* d_in, const int* in_sizes, int n_in,
                              void* d_out, int out_size)
{
    const float* lstm = (const float*)d_in[0];
    const float* fh   = (const float*)d_in[1];
    const float* Wq   = (const float*)d_in[2];
    const float* bq   = (const float*)d_in[3];
    const float* Wk   = (const float*)d_in[4];
    const float* bk   = (const float*)d_in[5];
    const float* Wv   = (const float*)d_in[6];
    const float* bv   = (const float*)d_in[7];

    const int BH = in_sizes[1];            // B * H
    const int B  = BH / 32;
    const int S  = in_sizes[0] / BH;
    const int nCh = (S + 1023) / 1024;     // 1024 rows per CTA

    float* out_ctx = (float*)d_out;                 // [B, 32]
    float* out_w   = out_ctx + (size_t)B * 32;      // [B, S]

    const int smemBytes = 4 * 4608 * (int)sizeof(float);   // 72 KB
    static int attrSet = 0;
    if (!attrSet) {
        cudaFuncSetAttribute(attn_main,
                             cudaFuncAttributeMaxDynamicSharedMemorySize,
                             smemBytes);
        attrSet = 1;
    }

    dim3 grid(nCh, B);
    attn_main<<<grid, 128, smemBytes>>>(lstm, fh, Wq, bq, Wk, bk, Wv, bv,
                                        out_w, S);

    dim3 ngrid((S / 4 + 255) / 256, B);
    attn_norm<<<ngrid, 256>>>(bk, out_ctx, out_w, S, nCh);
}

// round 13
// speedup vs baseline: 1.8868x; 1.2781x over previous
#include <cuda_runtime.h>
#include <math_constants.h>
#include <cstdint>

#define LOG2E 1.4426950408889634f

// Scratch (no allocations allowed): per-(b,chunk) partial L and ctx[32].
__device__ float g_pl[8192];
__device__ float g_pctx[8192 * 32];

// Non-volatile on purpose — pure register computation; ptxas schedules
// around the tensor-op latency.
__device__ __forceinline__ void mma_tf32(
    float& d0, float& d1, float& d2, float& d3,
    uint32_t a0, uint32_t a1, uint32_t a2, uint32_t a3,
    uint32_t b0, uint32_t b1)
{
    asm("mma.sync.aligned.m16n8k8.row.col.f32.tf32.tf32.f32 "
        "{%0,%1,%2,%3}, {%4,%5,%6,%7}, {%8,%9}, {%0,%1,%2,%3};"
        : "+f"(d0), "+f"(d1), "+f"(d2), "+f"(d3)
        : "r"(a0), "r"(a1), "r"(a2), "r"(a3), "r"(b0), "r"(b1));
}

// round-to-nearest tf32
__device__ __forceinline__ uint32_t tf32_rna(float x)
{
    uint32_t r;
    asm("cvt.rna.tf32.f32 %0, %1;" : "=r"(r) : "f"(x));
    return r;
}

// Stage one 32-row group (32 floats/row) into smem at row stride 36 floats.
__device__ __forceinline__
void stage_group(const float* __restrict__ gRowBase, int rowsLeft,
                 float* __restrict__ xb, int lane)
{
    const char* gsrc = (const char*)gRowBase;
    const int maxIdx = rowsLeft * 8 - 1;
    #pragma unroll
    for (int k = 0; k < 8; ++k) {
        const int idx = k * 32 + lane;               // 0..255 16B chunks
        const int row = idx >> 3, c = idx & 7;
        unsigned long long saddr =
            __cvta_generic_to_shared(xb + row * 36 + c * 4);
        const char* src = gsrc + (size_t)min(idx, maxIdx) * 16;
        asm volatile("cp.async.cg.shared.global [%0], [%1], 16;"
                     :: "l"(saddr), "l"(src));
    }
}

// ---------------------------------------------------------------------------
// Kernel 1: grid (nChunk, B), 128 threads, 4 CTAs/SM (36 KB smem each).
// CTA covers 1024 rows; warp sweeps 8 x 32-row groups, double-buffered
// cp.async. Keys GEMM: m16n8k8 tf32 single-pass (A and B rna-rounded;
// calibrated error ~1e-4 << 1e-3). tanh.approx score; unnormalized p -> out_w.
// ---------------------------------------------------------------------------
__global__ __launch_bounds__(128, 4)
void attn_main(const float* __restrict__ lstm, const float* __restrict__ fh,
               const float* __restrict__ Wq, const float* __restrict__ bq,
               const float* __restrict__ Wk, const float* __restrict__ bk,
               const float* __restrict__ Wv, const float* __restrict__ bv,
               float* __restrict__ out_w, int S)
{
    const int chunk = blockIdx.x;
    const int b     = blockIdx.y;
    const int tid   = threadIdx.x;
    const int w     = tid >> 5;
    const int lane  = tid & 31;
    const int g8    = lane >> 2;
    const int t4    = lane & 3;

    extern __shared__ __align__(16) float sX[];      // 4 warps * 2 * 1152

    __shared__ __align__(16) float sQC[32];
    __shared__ float sCtxW[128], sLw[4];

    float* xb0 = sX + w * 2304;                      // two 1152-float buffers
    const size_t rowB = (size_t)b * S;
    const int cbase = chunk * 1024;

    // ---- prefetch group 0 ----
    {
        const int base = cbase + w * 32;
        if (base < S)
            stage_group(lstm + (rowB + base) * 32, S - base, xb0, lane);
        asm volatile("cp.async.commit_group;");
    }

    // ---- prologue: query GEMV (overlaps group-0 DRAM latency) ----
    if (tid < 32) {
        float acc = bq[tid];
        #pragma unroll
        for (int h = 0; h < 32; ++h)
            acc = fmaf(fh[b * 32 + h], Wq[h * 32 + tid], acc);
        sQC[tid] = acc;
    }

    // ---- Wk fragments (tf32 rna): B[k][n] = Wk[k*32+n] ----
    uint32_t Bf[4][4][2];
    #pragma unroll
    for (int kt = 0; kt < 4; ++kt)
        #pragma unroll
        for (int nt = 0; nt < 4; ++nt) {
            const int n = nt * 8 + g8;
            Bf[kt][nt][0] = tf32_rna(Wk[(kt * 8 + t4) * 32 + n]);
            Bf[kt][nt][1] = tf32_rna(Wk[(kt * 8 + t4 + 4) * 32 + n]);
        }

    __syncthreads();

    // ---- per-lane column constants (slot s -> col = (s>>1)*8+2*t4+(s&1)) --
    float qbk[8], wvv[8];
    #pragma unroll
    for (int s = 0; s < 8; ++s) {
        const int col = (s >> 1) * 8 + 2 * t4 + (s & 1);
        wvv[s] = Wv[col];
        qbk[s] = sQC[col] + bk[col];
    }
    const float w1l = bv[0] * LOG2E;     // p = exp2(score*log2e + bv*log2e)

    float l = 0.f;
    float ctxD[8];
    #pragma unroll
    for (int s = 0; s < 8; ++s) ctxD[s] = 0.f;

    // ---- main sweep: 8 groups of 32 rows per warp ----
    #pragma unroll 1
    for (int gi = 0; gi < 8; ++gi) {
        if (gi + 1 < 8) {
            const int nb = cbase + (gi + 1) * 128 + w * 32;
            if (nb < S)
                stage_group(lstm + (rowB + nb) * 32, S - nb,
                            xb0 + ((gi + 1) & 1) * 1152, lane);
            asm volatile("cp.async.commit_group;");
            asm volatile("cp.async.wait_group 1;");
        } else {
            asm volatile("cp.async.wait_group 0;");
        }
        __syncwarp();

        const int gs = cbase + gi * 128 + w * 32;
        if (gs >= S) continue;
        const float* xg = xb0 + (gi & 1) * 1152;

        #pragma unroll 1
        for (int mt = 0; mt < 2; ++mt) {
            // ---- GEMM: D[16] = X[mt-tile] @ Wk (1-pass tf32) ----
            float D[16];
            #pragma unroll
            for (int e = 0; e < 16; ++e) D[e] = 0.f;

            #pragma unroll
            for (int kt = 0; kt < 4; ++kt) {
                const int abase = (mt * 16 + g8) * 36 + kt * 8 + t4;
                uint32_t a0 = tf32_rna(xg[abase]);
                uint32_t a1 = tf32_rna(xg[abase + 288]);   // +8 rows
                uint32_t a2 = tf32_rna(xg[abase + 4]);     // +4 k
                uint32_t a3 = tf32_rna(xg[abase + 292]);

                #pragma unroll
                for (int nt = 0; nt < 4; ++nt)
                    mma_tf32(D[nt * 4], D[nt * 4 + 1], D[nt * 4 + 2],
                             D[nt * 4 + 3], a0, a1, a2, a3,
                             Bf[kt][nt][0], Bf[kt][nt][1]);
            }

            // ---- epilogue: rows r0 = gs+mt*16+g8, r1 = r0+8 ----
            const int r0 = gs + mt * 16 + g8;
            const int r1 = r0 + 8;
            const bool v0 = r0 < S, v1 = r1 < S;

            float s0 = 0.f, s1 = 0.f;
            #pragma unroll
            for (int nt = 0; nt < 4; ++nt)
                #pragma unroll
                for (int c = 0; c < 4; ++c) {
                    const int e = nt * 4 + c;
                    const int s = nt * 2 + (c & 1);
                    float t;                          // HW tanh: 1 MUFU op
                    asm("tanh.approx.f32 %0, %1;"
                        : "=f"(t) : "f"(D[e] + qbk[s]));
                    if (c < 2) s0 = fmaf(t, wvv[s], s0);
                    else       s1 = fmaf(t, wvv[s], s1);
                }

            s0 += __shfl_xor_sync(0xffffffffu, s0, 1);
            s0 += __shfl_xor_sync(0xffffffffu, s0, 2);
            s1 += __shfl_xor_sync(0xffffffffu, s1, 1);
            s1 += __shfl_xor_sync(0xffffffffu, s1, 2);

            float p0, p1;
            asm("ex2.approx.f32 %0, %1;" : "=f"(p0)
                : "f"(fmaf(s0, LOG2E, w1l)));
            asm("ex2.approx.f32 %0, %1;" : "=f"(p1)
                : "f"(fmaf(s1, LOG2E, w1l)));
            if (!v0) p0 = 0.f;
            if (!v1) p1 = 0.f;

            if (t4 == 0) {                           // unnormalized p -> gmem
                if (v0) out_w[rowB + r0] = p0;
                if (v1) out_w[rowB + r1] = p1;
            }

            l += p0 + p1;
            #pragma unroll
            for (int nt = 0; nt < 4; ++nt)
                #pragma unroll
                for (int bit = 0; bit < 2; ++bit) {
                    const int s = nt * 2 + bit;
                    ctxD[s] = fmaf(p0, D[nt * 4 + bit],
                              fmaf(p1, D[nt * 4 + 2 + bit], ctxD[s]));
                }
        }
    }

    // ---- warp reduce: l (/4 quad dup) and ctxD ----
    #pragma unroll
    for (int off = 16; off; off >>= 1)
        l += __shfl_xor_sync(0xffffffffu, l, off);
    l *= 0.25f;

    #pragma unroll
    for (int s = 0; s < 8; ++s) {
        ctxD[s] += __shfl_xor_sync(0xffffffffu, ctxD[s], 4);
        ctxD[s] += __shfl_xor_sync(0xffffffffu, ctxD[s], 8);
        ctxD[s] += __shfl_xor_sync(0xffffffffu, ctxD[s], 16);
    }
    if (g8 == 0) {
        #pragma unroll
        for (int s = 0; s < 8; ++s) {
            const int col = (s >> 1) * 8 + 2 * t4 + (s & 1);
            sCtxW[w * 32 + col] = ctxD[s];
        }
    }
    if (lane == 0) sLw[w] = l;
    __syncthreads();

    // ---- per-CTA partial out ----
    if (tid < 32) {
        float L = 0.f, ct = 0.f;
        #pragma unroll
        for (int ww = 0; ww < 4; ++ww) {
            L  += sLw[ww];
            ct += sCtxW[ww * 32 + tid];
        }
        const int pc = b * gridDim.x + chunk;
        g_pctx[pc * 32 + tid] = ct;
        if (tid == 0) g_pl[pc] = L;
    }
}

// ---------------------------------------------------------------------------
// Kernel 2 (fused finish): every block recomputes L from the nCh partials;
// block x==0 also merges ctx. Then weights = p * (1/L): each thread handles
// two float4s (512 f4 per block).
// ---------------------------------------------------------------------------
__global__ __launch_bounds__(256)
void attn_norm(const float* __restrict__ bk, float* __restrict__ out_ctx,
               float* __restrict__ out_w, int S, int nCh)
{
    const int b   = blockIdx.y;
    const int tid = threadIdx.x;

    float L = 0.f;
    for (int c = 0; c < nCh; ++c) L += g_pl[b * nCh + c];
    const float inv = 1.f / L;

    if (blockIdx.x == 0 && tid < 32) {
        float ct = 0.f;
        for (int c = 0; c < nCh; ++c)
            ct += g_pctx[(b * nCh + c) * 32 + tid];
        out_ctx[b * 32 + tid] = fmaf(ct, inv, bk[tid]);   // + bk fold
    }

    float* base = out_w + (size_t)b * S;
    const int nF4 = S >> 2;
    float4* p4 = (float4*)base;
    const int i0 = blockIdx.x * 512 + tid;
    #pragma unroll
    for (int rep = 0; rep < 2; ++rep) {
        const int i = i0 + rep * 256;
        if (i < nF4) {
            float4 v = p4[i];
            v.x *= inv; v.y *= inv; v.z *= inv; v.w *= inv;
            p4[i] = v;
        }
    }
    // scalar tail (S not multiple of 4)
    for (int i = (nF4 << 2) + blockIdx.x * 256 + tid; i < S; i += gridDim.x * 256)
        base[i] *= inv;
}

// ---------------------------------------------------------------------------
extern "C" void kernel_launch(void* const* d_in, const int* in_sizes, int n_in,
                              void* d_out, int out_size)
{
    const float* lstm = (const float*)d_in[0];
    const float* fh   = (const float*)d_in[1];
    const float* Wq   = (const float*)d_in[2];
    const float* bq   = (const float*)d_in[3];
    const float* Wk   = (const float*)d_in[4];
    const float* bk   = (const float*)d_in[5];
    const float* Wv   = (const float*)d_in[6];
    const float* bv   = (const float*)d_in[7];

    const int BH = in_sizes[1];            // B * H
    const int B  = BH / 32;
    const int S  = in_sizes[0] / BH;
    const int nCh = (S + 1023) / 1024;     // 1024 rows per CTA

    float* out_ctx = (float*)d_out;                 // [B, 32]
    float* out_w   = out_ctx + (size_t)B * 32;      // [B, S]

    const int smemBytes = 4 * 2304 * (int)sizeof(float);   // 36 KB
    static int attrSet = 0;
    if (!attrSet) {
        cudaFuncSetAttribute(attn_main,
                             cudaFuncAttributeMaxDynamicSharedMemorySize,
                             smemBytes);
        attrSet = 1;
    }

    dim3 grid(nCh, B);
    attn_main<<<grid, 128, smemBytes>>>(lstm, fh, Wq, bq, Wk, bk, Wv, bv,
                                        out_w, S);

    dim3 ngrid((S / 4 + 511) / 512, B);
    attn_norm<<<ngrid, 256>>>(bk, out_ctx, out_w, S, nCh);
}